// round 3
// baseline (speedup 1.0000x reference)
#include <cuda_runtime.h>
#include <cstdint>

// Problem constants
#define BATCH   2048
#define CSUB    256
#define KDIM    256      // input dim == hidden dim
#define M_TILE  128      // batch rows per CTA
#define H_STR   260      // SMEM stride for H (x / h1) buffer: 260 % 32 == 4 -> conflict-free A frags
#define B_STR   264      // SMEM stride for W chunk buffer: 264 % 32 == 8 -> conflict-free B frags
#define KC      32       // K-chunk staged per iteration

// SMEM layout (floats): H[128*260] | sB[32*264] | sBias[256] | sW3[256] | rowsum[128]
#define SMEM_FLOATS (128*H_STR + 32*B_STR + 256 + 256 + 128)
#define SMEM_BYTES  (SMEM_FLOATS * 4)

__device__ __forceinline__ uint32_t f2tf32(float f) {
    uint32_t u;
    asm("cvt.rna.tf32.f32 %0, %1;" : "=r"(u) : "f"(f));
    return u;
}

__device__ __forceinline__ void mma_tf32(float* d,
                                         uint32_t a0, uint32_t a1, uint32_t a2, uint32_t a3,
                                         uint32_t b0, uint32_t b1) {
    asm volatile(
        "mma.sync.aligned.m16n8k8.row.col.f32.tf32.tf32.f32 "
        "{%0,%1,%2,%3}, {%4,%5,%6,%7}, {%8,%9}, {%0,%1,%2,%3};"
        : "+f"(d[0]), "+f"(d[1]), "+f"(d[2]), "+f"(d[3])
        : "r"(a0), "r"(a1), "r"(a2), "r"(a3), "r"(b0), "r"(b1));
}

__global__ __launch_bounds__(512, 1)
void rfprism_kernel(const float* __restrict__ x,
                    const float* __restrict__ W1,
                    const float* __restrict__ b1,
                    const float* __restrict__ W2,
                    const float* __restrict__ b2,
                    const float* __restrict__ W3,
                    const float* __restrict__ b3,
                    float* __restrict__ out) {
    extern __shared__ float smem[];
    float* Hs     = smem;                      // [128][H_STR] tf32-as-float, x then relu(h1)
    float* sB     = Hs + 128 * H_STR;          // [32][B_STR]  staged W chunk (tf32)
    float* sBias  = sB + 32 * B_STR;           // [256] current layer bias (fp32)
    float* sW3    = sBias + 256;               // [256] W3[c] (fp32)
    float* rowsum = sW3 + 256;                 // [128] layer-3 reduction

    const int tid  = threadIdx.x;
    const int c    = blockIdx.y;
    const int b0   = blockIdx.x * M_TILE;
    const int lane = tid & 31;
    const int warp = tid >> 5;
    const int wm   = warp >> 2;     // 0..3  (M)
    const int wn   = warp & 3;      // 0..3  (N)
    const int g    = lane >> 2;     // groupID 0..7
    const int tig  = lane & 3;      // thread-in-group 0..3

    // ---------- prologue: x tile -> Hs (tf32), b1, W3, rowsum=0 ----------
    {
        const int row = tid >> 2;           // 0..127
        const int seg = tid & 3;            // 0..3, 64 cols each
        const float4* src = reinterpret_cast<const float4*>(
            x + (size_t)(b0 + row) * KDIM + seg * 64);
        float* dst = Hs + row * H_STR + seg * 64;
        #pragma unroll
        for (int j = 0; j < 16; ++j) {
            float4 v = src[j];
            float4 o;
            o.x = __uint_as_float(f2tf32(v.x));
            o.y = __uint_as_float(f2tf32(v.y));
            o.z = __uint_as_float(f2tf32(v.z));
            o.w = __uint_as_float(f2tf32(v.w));
            reinterpret_cast<float4*>(dst)[j] = o;
        }
    }
    if (tid < 64) {
        reinterpret_cast<float4*>(sBias)[tid] =
            reinterpret_cast<const float4*>(b1 + (size_t)c * 256)[tid];
    } else if (tid < 128) {
        reinterpret_cast<float4*>(sW3)[tid - 64] =
            reinterpret_cast<const float4*>(W3 + (size_t)c * 256)[tid - 64];
    } else if (tid < 256) {
        rowsum[tid - 128] = 0.0f;
    }
    __syncthreads();

    float acc[2][8][4];

    #pragma unroll 1
    for (int layer = 0; layer < 2; ++layer) {
        const float* Wg = (layer == 0 ? W1 : W2) + (size_t)c * (KDIM * 256);

        #pragma unroll
        for (int m = 0; m < 2; ++m)
            #pragma unroll
            for (int t = 0; t < 8; ++t)
                #pragma unroll
                for (int r = 0; r < 4; ++r)
                    acc[m][t][r] = 0.0f;

        #pragma unroll 1
        for (int kc = 0; kc < KDIM / KC; ++kc) {
            if (layer != 0 || kc != 0) __syncthreads();   // protect sB / sBias overwrite

            // stage W chunk [32][256] -> sB (tf32)
            {
                const int row = tid >> 4;        // 0..31
                const int seg = tid & 15;        // 16 cols each
                const float4* src = reinterpret_cast<const float4*>(
                    Wg + (size_t)(kc * KC + row) * 256 + seg * 16);
                float* dst = sB + row * B_STR + seg * 16;
                #pragma unroll
                for (int j = 0; j < 4; ++j) {
                    float4 v = src[j];
                    float4 o;
                    o.x = __uint_as_float(f2tf32(v.x));
                    o.y = __uint_as_float(f2tf32(v.y));
                    o.z = __uint_as_float(f2tf32(v.z));
                    o.w = __uint_as_float(f2tf32(v.w));
                    reinterpret_cast<float4*>(dst)[j] = o;
                }
            }
            if (layer == 1 && kc == 0 && tid < 64) {      // b2 replaces b1
                reinterpret_cast<float4*>(sBias)[tid] =
                    reinterpret_cast<const float4*>(b2 + (size_t)c * 256)[tid];
            }
            __syncthreads();

            // compute: 4 k-steps of 8
            #pragma unroll
            for (int k8 = 0; k8 < 4; ++k8) {
                const int kb = k8 * 8;
                uint32_t bf[8][2];
                #pragma unroll
                for (int t = 0; t < 8; ++t) {
                    const int n = wn * 64 + t * 8 + g;
                    bf[t][0] = __float_as_uint(sB[(kb + tig)     * B_STR + n]);
                    bf[t][1] = __float_as_uint(sB[(kb + tig + 4) * B_STR + n]);
                }
                const int ka = kc * KC + kb;
                #pragma unroll
                for (int m = 0; m < 2; ++m) {
                    const int r = wm * 32 + m * 16;
                    uint32_t a0 = __float_as_uint(Hs[(r + g)     * H_STR + ka + tig]);
                    uint32_t a1 = __float_as_uint(Hs[(r + g + 8) * H_STR + ka + tig]);
                    uint32_t a2 = __float_as_uint(Hs[(r + g)     * H_STR + ka + tig + 4]);
                    uint32_t a3 = __float_as_uint(Hs[(r + g + 8) * H_STR + ka + tig + 4]);
                    #pragma unroll
                    for (int t = 0; t < 8; ++t)
                        mma_tf32(acc[m][t], a0, a1, a2, a3, bf[t][0], bf[t][1]);
                }
            }
        }
        __syncthreads();   // all compute (reads of Hs/sB) done

        if (layer == 0) {
            // epilogue 1: Hs = tf32(relu(acc + b1))
            #pragma unroll
            for (int m = 0; m < 2; ++m) {
                const int r0 = wm * 32 + m * 16 + g;
                const int r1 = r0 + 8;
                #pragma unroll
                for (int t = 0; t < 8; ++t) {
                    const int c0 = wn * 64 + t * 8 + 2 * tig;
                    float v00 = fmaxf(acc[m][t][0] + sBias[c0],     0.0f);
                    float v01 = fmaxf(acc[m][t][1] + sBias[c0 + 1], 0.0f);
                    float v10 = fmaxf(acc[m][t][2] + sBias[c0],     0.0f);
                    float v11 = fmaxf(acc[m][t][3] + sBias[c0 + 1], 0.0f);
                    Hs[r0 * H_STR + c0]     = __uint_as_float(f2tf32(v00));
                    Hs[r0 * H_STR + c0 + 1] = __uint_as_float(f2tf32(v01));
                    Hs[r1 * H_STR + c0]     = __uint_as_float(f2tf32(v10));
                    Hs[r1 * H_STR + c0 + 1] = __uint_as_float(f2tf32(v11));
                }
            }
        } else {
            // epilogue 2 + layer 3: row-dot with W3, fused relu(.. + b2)
            #pragma unroll
            for (int m = 0; m < 2; ++m) {
                const int r0 = wm * 32 + m * 16 + g;
                const int r1 = r0 + 8;
                float s0 = 0.0f, s1 = 0.0f;
                #pragma unroll
                for (int t = 0; t < 8; ++t) {
                    const int c0 = wn * 64 + t * 8 + 2 * tig;
                    const float w0 = sW3[c0], w1 = sW3[c0 + 1];
                    const float bb0 = sBias[c0], bb1 = sBias[c0 + 1];
                    s0 += fmaxf(acc[m][t][0] + bb0, 0.0f) * w0
                        + fmaxf(acc[m][t][1] + bb1, 0.0f) * w1;
                    s1 += fmaxf(acc[m][t][2] + bb0, 0.0f) * w0
                        + fmaxf(acc[m][t][3] + bb1, 0.0f) * w1;
                }
                s0 += __shfl_xor_sync(0xffffffffu, s0, 1);
                s0 += __shfl_xor_sync(0xffffffffu, s0, 2);
                s1 += __shfl_xor_sync(0xffffffffu, s1, 1);
                s1 += __shfl_xor_sync(0xffffffffu, s1, 2);
                if (tig == 0) {
                    atomicAdd(&rowsum[r0], s0);
                    atomicAdd(&rowsum[r1], s1);
                }
            }
        }
    }

    __syncthreads();
    if (tid < M_TILE) {
        out[(size_t)(b0 + tid) * CSUB + c] = rowsum[tid] + b3[c];
    }
}

extern "C" void kernel_launch(void* const* d_in, const int* in_sizes, int n_in,
                              void* d_out, int out_size) {
    (void)in_sizes; (void)n_in; (void)out_size;
    const float* x  = (const float*)d_in[0];
    const float* W1 = (const float*)d_in[1];
    const float* b1 = (const float*)d_in[2];
    const float* W2 = (const float*)d_in[3];
    const float* b2 = (const float*)d_in[4];
    const float* W3 = (const float*)d_in[5];
    const float* b3 = (const float*)d_in[6];
    float* out = (float*)d_out;

    cudaFuncSetAttribute(rfprism_kernel,
                         cudaFuncAttributeMaxDynamicSharedMemorySize, SMEM_BYTES);

    dim3 grid(BATCH / M_TILE, CSUB);   // (16, 256)
    rfprism_kernel<<<grid, 512, SMEM_BYTES>>>(x, W1, b1, W2, b2, W3, b3, out);
}

// round 7
// speedup vs baseline: 1.5482x; 1.5482x over previous
#include <cuda_runtime.h>
#include <cstdint>

// ---------------- problem constants ----------------
#define BATCH   2048
#define CSUB    256
#define KDIM    256
#define NDIM    256
#define MTILE   128

#define HS_STR  260          // floats; 260%32==4 -> conflict-free A fragment LDS
#define BS_STR  264          // floats; 264%32==8 -> conflict-free B fragment LDS

#define A_BYTES   (128 * HS_STR * 4)            // 133120
#define B_OFF     A_BYTES
#define B_BYTES   (32 * BS_STR * 4)             // 33792 per buffer (x2)
#define BIAS_OFF  (B_OFF + 2 * B_BYTES)         // 200704
#define W3_OFF    (BIAS_OFF + 1024)
#define RS_OFF    (W3_OFF + 1024)
#define SMEM_BYTES (RS_OFF + 512)               // 203264

// ---------------- scratch (pre-rounded tf32 operands) ----------------
__device__ float g_W1t[CSUB * KDIM * NDIM];     // 64 MiB
__device__ float g_W2t[CSUB * KDIM * NDIM];     // 64 MiB
__device__ float g_xt[BATCH * KDIM];            // 2 MiB

// ---------------- helpers ----------------
__device__ __forceinline__ uint32_t f2tf32(float f) {
    uint32_t u;
    asm("cvt.rna.tf32.f32 %0, %1;" : "=r"(u) : "f"(f));
    return u;
}

__device__ __forceinline__ uint32_t smem_u32(const void* p) {
    uint32_t a;
    asm("{ .reg .u64 t; cvta.to.shared.u64 t, %1; cvt.u32.u64 %0, t; }" : "=r"(a) : "l"(p));
    return a;
}

__device__ __forceinline__ void cp16(uint32_t dst, const void* src) {
    asm volatile("cp.async.cg.shared.global [%0], [%1], 16;" :: "r"(dst), "l"(src) : "memory");
}
#define CP_COMMIT() asm volatile("cp.async.commit_group;" ::: "memory")
#define CP_WAIT1()  asm volatile("cp.async.wait_group 1;"  ::: "memory")
#define CP_WAIT0()  asm volatile("cp.async.wait_group 0;"  ::: "memory")

__device__ __forceinline__ void mma_tf32(float* d,
                                         uint32_t a0, uint32_t a1, uint32_t a2, uint32_t a3,
                                         uint32_t b0, uint32_t b1) {
    asm volatile(
        "mma.sync.aligned.m16n8k8.row.col.f32.tf32.tf32.f32 "
        "{%0,%1,%2,%3}, {%4,%5,%6,%7}, {%8,%9}, {%0,%1,%2,%3};"
        : "+f"(d[0]), "+f"(d[1]), "+f"(d[2]), "+f"(d[3])
        : "r"(a0), "r"(a1), "r"(a2), "r"(a3), "r"(b0), "r"(b1));
}

// ---------------- prepass: round to tf32 (rna), elementwise ----------------
__global__ void round_tf32_kernel(const float* __restrict__ src, int sel, int n4) {
    float* dst = (sel == 0) ? g_W1t : (sel == 1) ? g_W2t : g_xt;
    int i = blockIdx.x * blockDim.x + threadIdx.x;
    const int stride = gridDim.x * blockDim.x;
    for (; i < n4; i += stride) {
        float4 v = reinterpret_cast<const float4*>(src)[i];
        uint4 u;
        u.x = f2tf32(v.x); u.y = f2tf32(v.y);
        u.z = f2tf32(v.z); u.w = f2tf32(v.w);
        reinterpret_cast<uint4*>(dst)[i] = u;
    }
}

// ---------------- staging ----------------
__device__ __forceinline__ void stage_B(uint32_t sb, int bufsel, const float* src, int tid) {
    const uint32_t base = sb + B_OFF + bufsel * B_BYTES;
    #pragma unroll
    for (int i = 0; i < 4; ++i) {
        const int u  = tid + i * 512;       // 2048 x 16B units = 32 rows x 1024 B
        const int k  = u >> 6;
        const int n4 = u & 63;
        cp16(base + k * (BS_STR * 4) + n4 * 16, src + u * 4);
    }
    CP_COMMIT();
}

// ---------------- main kernel ----------------
__global__ __launch_bounds__(512, 1)
void rfprism_main(const float* __restrict__ b1,
                  const float* __restrict__ b2,
                  const float* __restrict__ W3,
                  const float* __restrict__ b3,
                  float* __restrict__ out) {
    extern __shared__ char smem[];
    const uint32_t sb = smem_u32(smem);
    float* Hs     = (float*)smem;
    float* sBias  = (float*)(smem + BIAS_OFF);
    float* sW3v   = (float*)(smem + W3_OFF);
    float* rowsum = (float*)(smem + RS_OFF);

    const int tid  = threadIdx.x;
    const int warp = tid >> 5;
    const int lane = tid & 31;
    const int c    = blockIdx.y;
    const int b0   = blockIdx.x * MTILE;
    const int wm   = warp >> 2;
    const int wn   = warp & 3;
    const int g    = lane >> 2;
    const int tig  = lane & 3;

    // ---- prologue: async-copy A (x tile, FULL 8192 16B units) + first two W1 chunks ----
    {
        #pragma unroll
        for (int i = 0; i < 16; ++i) {
            const int u   = tid + i * 512;      // 0..8191
            const int row = u >> 6;             // 64 units (1024 B) per row
            const int k4  = u & 63;
            cp16(sb + row * (HS_STR * 4) + k4 * 16,
                 g_xt + (size_t)(b0 + row) * KDIM + k4 * 4);
        }
        CP_COMMIT();
    }
    stage_B(sb, 0, g_W1t + (size_t)c * (KDIM * NDIM), tid);
    stage_B(sb, 1, g_W1t + (size_t)c * (KDIM * NDIM) + 8192, tid);

    if (tid < 64) {
        ((float4*)sBias)[tid] = ((const float4*)(b1 + (size_t)c * 256))[tid];
    } else if (tid < 128) {
        ((float4*)sW3v)[tid - 64] = ((const float4*)(W3 + (size_t)c * 256))[tid - 64];
    } else if (tid < 256) {
        rowsum[tid - 128] = 0.0f;
    }

    float acc[2][8][4];
    #pragma unroll
    for (int m = 0; m < 2; ++m)
        #pragma unroll
        for (int t = 0; t < 8; ++t)
            #pragma unroll
            for (int r = 0; r < 4; ++r)
                acc[m][t][r] = 0.0f;

    // ---- pipelined mainloop over 16 chunks (8 per layer) ----
    #pragma unroll 1
    for (int kk = 0; kk < 16; ++kk) {
        if (kk < 15) { CP_WAIT1(); } else { CP_WAIT0(); }
        __syncthreads();

        const float* sBb = (const float*)(smem + B_OFF + (kk & 1) * B_BYTES);

        #pragma unroll
        for (int k8 = 0; k8 < 4; ++k8) {
            const int kb = k8 * 8;
            uint32_t bf[8][2];
            #pragma unroll
            for (int t = 0; t < 8; ++t) {
                const int n = wn * 64 + t * 8 + g;
                bf[t][0] = __float_as_uint(sBb[(kb + tig)     * BS_STR + n]);
                bf[t][1] = __float_as_uint(sBb[(kb + tig + 4) * BS_STR + n]);
            }
            const int ka = (kk & 7) * 32 + kb;
            #pragma unroll
            for (int m = 0; m < 2; ++m) {
                const int r = wm * 32 + m * 16;
                uint32_t a0 = __float_as_uint(Hs[(r + g)     * HS_STR + ka + tig]);
                uint32_t a1 = __float_as_uint(Hs[(r + g + 8) * HS_STR + ka + tig]);
                uint32_t a2 = __float_as_uint(Hs[(r + g)     * HS_STR + ka + tig + 4]);
                uint32_t a3 = __float_as_uint(Hs[(r + g + 8) * HS_STR + ka + tig + 4]);
                #pragma unroll
                for (int t = 0; t < 8; ++t)
                    mma_tf32(acc[m][t], a0, a1, a2, a3, bf[t][0], bf[t][1]);
            }
        }
        __syncthreads();   // all reads of buf[kk&1] (and, at kk==7, of Hs) done

        // issue copy of chunk kk+2 into the buffer just freed (overlaps next compute)
        if (kk + 2 < 16) {
            const int t2 = kk + 2;
            const float* W = (t2 < 8) ? g_W1t : g_W2t;
            stage_B(sb, kk & 1, W + (size_t)c * (KDIM * NDIM) + (size_t)(t2 & 7) * 8192, tid);
        }

        if (kk == 7) {
            // epilogue 1: Hs = tf32(relu(acc + b1)); own rows only
            #pragma unroll
            for (int m = 0; m < 2; ++m) {
                const int r0 = wm * 32 + m * 16 + g;
                const int r1 = r0 + 8;
                #pragma unroll
                for (int t = 0; t < 8; ++t) {
                    const int c0 = wn * 64 + t * 8 + 2 * tig;
                    float v00 = fmaxf(acc[m][t][0] + sBias[c0],     0.0f);
                    float v01 = fmaxf(acc[m][t][1] + sBias[c0 + 1], 0.0f);
                    float v10 = fmaxf(acc[m][t][2] + sBias[c0],     0.0f);
                    float v11 = fmaxf(acc[m][t][3] + sBias[c0 + 1], 0.0f);
                    Hs[r0 * HS_STR + c0]     = __uint_as_float(f2tf32(v00));
                    Hs[r0 * HS_STR + c0 + 1] = __uint_as_float(f2tf32(v01));
                    Hs[r1 * HS_STR + c0]     = __uint_as_float(f2tf32(v10));
                    Hs[r1 * HS_STR + c0 + 1] = __uint_as_float(f2tf32(v11));
                }
            }
            __syncthreads();            // Hs writes + b1 reads done everywhere
            if (tid < 64)               // b2 replaces b1 (read only in epilogue 2)
                ((float4*)sBias)[tid] = ((const float4*)(b2 + (size_t)c * 256))[tid];
            #pragma unroll
            for (int m = 0; m < 2; ++m)
                #pragma unroll
                for (int t = 0; t < 8; ++t)
                    #pragma unroll
                    for (int r = 0; r < 4; ++r)
                        acc[m][t][r] = 0.0f;
        }
    }

    // ---- epilogue 2 + layer 3: rowsum += relu(acc + b2) . W3 ----
    #pragma unroll
    for (int m = 0; m < 2; ++m) {
        const int r0 = wm * 32 + m * 16 + g;
        const int r1 = r0 + 8;
        float s0 = 0.0f, s1 = 0.0f;
        #pragma unroll
        for (int t = 0; t < 8; ++t) {
            const int c0 = wn * 64 + t * 8 + 2 * tig;
            const float w0 = sW3v[c0], w1 = sW3v[c0 + 1];
            const float bb0 = sBias[c0], bb1 = sBias[c0 + 1];
            s0 += fmaxf(acc[m][t][0] + bb0, 0.0f) * w0
                + fmaxf(acc[m][t][1] + bb1, 0.0f) * w1;
            s1 += fmaxf(acc[m][t][2] + bb0, 0.0f) * w0
                + fmaxf(acc[m][t][3] + bb1, 0.0f) * w1;
        }
        s0 += __shfl_xor_sync(0xffffffffu, s0, 1);
        s0 += __shfl_xor_sync(0xffffffffu, s0, 2);
        s1 += __shfl_xor_sync(0xffffffffu, s1, 1);
        s1 += __shfl_xor_sync(0xffffffffu, s1, 2);
        if (tig == 0) {
            atomicAdd(&rowsum[r0], s0);
            atomicAdd(&rowsum[r1], s1);
        }
    }

    __syncthreads();
    if (tid < MTILE)
        out[(size_t)(b0 + tid) * CSUB + c] = rowsum[tid] + b3[c];
}

extern "C" void kernel_launch(void* const* d_in, const int* in_sizes, int n_in,
                              void* d_out, int out_size) {
    (void)in_sizes; (void)n_in; (void)out_size;
    const float* x  = (const float*)d_in[0];
    const float* W1 = (const float*)d_in[1];
    const float* b1 = (const float*)d_in[2];
    const float* W2 = (const float*)d_in[3];
    const float* b2 = (const float*)d_in[4];
    const float* W3 = (const float*)d_in[5];
    const float* b3 = (const float*)d_in[6];
    float* out = (float*)d_out;

    // prepass: tf32-round W1, W2, x into scratch
    const int nW4 = (CSUB * KDIM * NDIM) / 4;    // 4,194,304
    const int nX4 = (BATCH * KDIM) / 4;          // 131,072
    round_tf32_kernel<<<4096, 256>>>(W1, 0, nW4);
    round_tf32_kernel<<<4096, 256>>>(W2, 1, nW4);
    round_tf32_kernel<<<512, 256>>>(x,  2, nX4);

    cudaFuncSetAttribute(rfprism_main,
                         cudaFuncAttributeMaxDynamicSharedMemorySize, SMEM_BYTES);
    dim3 grid(BATCH / MTILE, CSUB);   // (16, 256)
    rfprism_main<<<grid, 512, SMEM_BYTES>>>(b1, b2, W3, b3, out);
}